// round 16
// baseline (speedup 1.0000x reference)
#include <cuda_runtime.h>
#include <cstdint>

// 3-level db4 wavedec (periodization) along axis 1 of (64, 4096, 64) fp32.
// Output rows: [cA3 (512) | cD3 (512) | cD2 (1024) | cD1 (2048)] x 64 feats.
//
// FINAL (R6 lock-in): best timed variant of the campaign (27.10 us).
// - Each thread owns 4 features (packed f32x2 FMA via fma.rn.f32x2,
//   128-bit global/shared memory ops): halves issue vs scalar/float2.
// - Batched 14-row window loads (MLP ~14) hide L2 latency.
// - Detail filter reuses the approx bank: RHI[t] = s(t)*RLO[7-t], sign
//   uniform per loaded row -> one XOR pair per odd row, 8 fewer u64 consts.
// - Level 1 reads x directly from global (coalesced; halo hits L1/L2),
//   cA1/cA2 staged in static smem, cD* streamed straight to global.
// - lb(256,3): 76 regs, no spills; 3 CTAs/SM.

#define NTHREADS 256
#define A1_ROWS  82   // valid local cA1 rows
#define A2_ROWS  38   // valid local cA2 rows
#define A1_CAP   88
#define A2_CAP   40

__device__ __forceinline__ void fma2(unsigned long long& acc,
                                     unsigned long long w,
                                     unsigned long long c) {
    asm("fma.rn.f32x2 %0, %1, %2, %0;" : "+l"(acc) : "l"(w), "l"(c));
}

__device__ __forceinline__ unsigned long long pneg(unsigned long long v) {
    return v ^ 0x8000000080000000ull;
}

// consume batched window v[14] into 4-row accumulators:
// a[q] += v[2q+t]*RLO[t];  d[q] += s(t)*v[2q+t]*RLO[7-t]
#define CONSUME_WINDOW                                              \
    _Pragma("unroll")                                               \
    for (int t = 0; t < 14; ++t) {                                  \
        const unsigned long long WL = v[t].x, WH = v[t].y;          \
        const unsigned long long nWL = (t & 1) ? pneg(WL) : WL;     \
        const unsigned long long nWH = (t & 1) ? pneg(WH) : WH;     \
        _Pragma("unroll")                                           \
        for (int q = 0; q < 4; ++q) {                               \
            const int tt = t - 2 * q;                               \
            if (tt >= 0 && tt < 8) {                                \
                fma2(aL[q], WL, clo[tt]);                           \
                fma2(aH[q], WH, clo[tt]);                           \
                fma2(dL[q], nWL, clo[7 - tt]);                      \
                fma2(dH[q], nWH, clo[7 - tt]);                      \
            }                                                       \
        }                                                           \
    }

__global__ void __launch_bounds__(NTHREADS, 3)
wavedec_kernel(const float* __restrict__ x, float* __restrict__ out) {
    __shared__ ulonglong2 s_a1[A1_CAP * 16];
    __shared__ ulonglong2 s_a2[A2_CAP * 16];

    const int tid  = threadIdx.x;
    const int f4   = tid & 15;    // float4 feature lane (64 floats = 16 float4)
    const int grp  = tid >> 4;    // 0..15, each group: 4 consecutive rows/pass
    const int tile = blockIdx.x;  // 0..31
    const int b    = blockIdx.y;  // 0..63

    // Reversed approx filter: out_a[i] = sum_t src[2i+t] * RLO[t]
    const float RLO[8] = {
         0.23037781330885523f,  0.7148465705525415f,   0.6308807679295904f,
        -0.02798376941698385f, -0.18703481171888114f,  0.030841381835986965f,
         0.032883011666982945f, -0.010597401784997278f };

    unsigned long long clo[8];
#pragma unroll
    for (int t = 0; t < 8; ++t)
        clo[t] = (unsigned long long)__float_as_uint(RLO[t]) * 0x100000001ull;

    const ulonglong2* __restrict__ xb4 =
        reinterpret_cast<const ulonglong2*>(x + (size_t)b * 4096 * 64);
    ulonglong2* __restrict__ ob4 =
        reinterpret_cast<ulonglong2*>(out + (size_t)b * 4096 * 64);

    const int g0 = 128 * tile - 42;  // global x row of local window origin

    // ---- Level 1: x (global) -> cA1 (smem) + cD1 (global) ----
#pragma unroll
    for (int pass = 0; pass < 2; ++pass) {
        const int i0 = pass * 64 + grp * 4;
        if (i0 < A1_ROWS) {
            unsigned long long aL[4] = {}, aH[4] = {}, dL[4] = {}, dH[4] = {};
            ulonglong2 v[14];
            const int r0 = g0 + 2 * i0;
            if (r0 >= 0 && r0 <= 4096 - 14) {
                const ulonglong2* p = xb4 + (size_t)r0 * 16 + f4;
#pragma unroll
                for (int t = 0; t < 14; ++t)
                    v[t] = p[t * 16];
            } else {
#pragma unroll
                for (int t = 0; t < 14; ++t) {
                    const int r = (r0 + t + 4096) & 4095;
                    v[t] = xb4[(size_t)r * 16 + f4];
                }
            }
            CONSUME_WINDOW
#pragma unroll
            for (int q = 0; q < 4; ++q) {
                const int i = i0 + q;          // max 83 < A1_CAP
                s_a1[i * 16 + f4] = make_ulonglong2(aL[q], aH[q]);
                if (i >= 18 && i < A1_ROWS)
                    ob4[(size_t)(2048 + 64 * tile + (i - 18)) * 16 + f4] =
                        make_ulonglong2(dL[q], dH[q]);
            }
        }
    }
    __syncthreads();

    // ---- Level 2: cA1 (smem) -> cA2 (smem) + cD2 (global) ----
    {
        const int i0 = grp * 4;
        if (i0 < A2_ROWS) {
            unsigned long long aL[4] = {}, aH[4] = {}, dL[4] = {}, dH[4] = {};
            ulonglong2 v[14];
            const ulonglong2* p = s_a1 + (size_t)(2 * i0) * 16 + f4;
#pragma unroll
            for (int t = 0; t < 14; ++t)
                v[t] = p[t * 16];
            CONSUME_WINDOW
#pragma unroll
            for (int q = 0; q < 4; ++q) {
                const int i = i0 + q;          // max 39 < A2_CAP
                s_a2[i * 16 + f4] = make_ulonglong2(aL[q], aH[q]);
                if (i >= 6 && i < A2_ROWS)
                    ob4[(size_t)(1024 + 32 * tile + (i - 6)) * 16 + f4] =
                        make_ulonglong2(dL[q], dH[q]);
            }
        }
    }
    __syncthreads();

    // ---- Level 3: cA2 (smem) -> cA3 + cD3 (global) ----
    {
        const int i0 = grp * 4;
        if (i0 < 16) {
            unsigned long long aL[4] = {}, aH[4] = {}, dL[4] = {}, dH[4] = {};
            ulonglong2 v[14];
            const ulonglong2* p = s_a2 + (size_t)(2 * i0) * 16 + f4;
#pragma unroll
            for (int t = 0; t < 14; ++t)
                v[t] = p[t * 16];
            CONSUME_WINDOW
#pragma unroll
            for (int q = 0; q < 4; ++q) {
                const int i = i0 + q;
                ob4[(size_t)(16 * tile + i) * 16 + f4] =
                    make_ulonglong2(aL[q], aH[q]);
                ob4[(size_t)(512 + 16 * tile + i) * 16 + f4] =
                    make_ulonglong2(dL[q], dH[q]);
            }
        }
    }
}

extern "C" void kernel_launch(void* const* d_in, const int* in_sizes, int n_in,
                              void* d_out, int out_size) {
    const float* x = (const float*)d_in[0];
    float* out = (float*)d_out;
    dim3 grid(32, 64);
    wavedec_kernel<<<grid, NTHREADS>>>(x, out);
}

// round 17
// speedup vs baseline: 1.0354x; 1.0354x over previous
#include <cuda_runtime.h>
#include <cstdint>

// 3-level db4 wavedec (periodization) along axis 1 of (64, 4096, 64) fp32.
// Output rows: [cA3 (512) | cD3 (512) | cD2 (1024) | cD1 (2048)] x 64 feats.
//
// FINAL (R15): best device-time variant of the campaign (ncu 22.98 us).
// - Each thread owns 4 features: packed f32x2 FMA (fma.rn.f32x2) + 128-bit
//   global/shared memory ops halve issue vs scalar forms.
// - TWO packed filter banks (clo/chi) -> no per-row sign XORs (lowest alu%).
// - Batched 14-row window loads (MLP ~14) hide L2 latency.
// - ld.global.nc for read-only x; st.global.cs (evict-first) for outputs so
//   the input stays L2-resident across graph replays.
// - lb(256,3): 78 regs, no spills; 3 CTAs/SM.

#define NTHREADS 256
#define A1_ROWS  82   // valid local cA1 rows
#define A2_ROWS  38   // valid local cA2 rows
#define A1_CAP   88
#define A2_CAP   40

__device__ __forceinline__ void fma2(unsigned long long& acc,
                                     unsigned long long w,
                                     unsigned long long c) {
    asm("fma.rn.f32x2 %0, %1, %2, %0;" : "+l"(acc) : "l"(w), "l"(c));
}

__device__ __forceinline__ ulonglong2 ldg_nc(const ulonglong2* p) {
    ulonglong2 r;
    asm("ld.global.nc.v2.u64 {%0, %1}, [%2];"
        : "=l"(r.x), "=l"(r.y) : "l"(p));
    return r;
}

__device__ __forceinline__ void stg_cs(ulonglong2* p,
                                       unsigned long long a,
                                       unsigned long long b) {
    asm volatile("st.global.cs.v2.u64 [%0], {%1, %2};"
                 :: "l"(p), "l"(a), "l"(b) : "memory");
}

// accumulate window row T into the 4-row output accumulators
#define ACC4(WL, WH, T)                                   \
    {                                                     \
        _Pragma("unroll")                                 \
        for (int q = 0; q < 4; ++q) {                     \
            const int tt = (T) - 2 * q;                   \
            if (tt >= 0 && tt < 8) {                      \
                fma2(aL[q], (WL), clo[tt]);               \
                fma2(aH[q], (WH), clo[tt]);               \
                fma2(dL[q], (WL), chi[tt]);               \
                fma2(dH[q], (WH), chi[tt]);               \
            }                                             \
        }                                                 \
    }

__global__ void __launch_bounds__(NTHREADS, 3)
wavedec_kernel(const float* __restrict__ x, float* __restrict__ out) {
    __shared__ ulonglong2 s_a1[A1_CAP * 16];
    __shared__ ulonglong2 s_a2[A2_CAP * 16];

    const int tid  = threadIdx.x;
    const int f4   = tid & 15;    // float4 feature lane (64 floats = 16 float4)
    const int grp  = tid >> 4;    // 0..15, each group: 4 consecutive rows/pass
    const int tile = blockIdx.x;  // 0..31
    const int b    = blockIdx.y;  // 0..63

    // Reversed db4 filters: out[i] = sum_t src[2i+t] * R*[t]
    const float RLO[8] = {
         0.23037781330885523f,  0.7148465705525415f,   0.6308807679295904f,
        -0.02798376941698385f, -0.18703481171888114f,  0.030841381835986965f,
         0.032883011666982945f, -0.010597401784997278f };
    const float RHI[8] = {
        -0.010597401784997278f, -0.032883011666982945f, 0.030841381835986965f,
         0.18703481171888114f,  -0.02798376941698385f, -0.6308807679295904f,
         0.7148465705525415f,   -0.23037781330885523f };

    // pack each coefficient into both f32 lanes of a 64-bit reg
    unsigned long long clo[8], chi[8];
#pragma unroll
    for (int t = 0; t < 8; ++t) {
        clo[t] = (unsigned long long)__float_as_uint(RLO[t]) * 0x100000001ull;
        chi[t] = (unsigned long long)__float_as_uint(RHI[t]) * 0x100000001ull;
    }

    const ulonglong2* __restrict__ xb4 =
        reinterpret_cast<const ulonglong2*>(x + (size_t)b * 4096 * 64);
    ulonglong2* __restrict__ ob4 =
        reinterpret_cast<ulonglong2*>(out + (size_t)b * 4096 * 64);

    const int g0 = 128 * tile - 42;  // global x row of local window origin

    // ---- Level 1: x (global) -> cA1 (smem) + cD1 (global) ----
#pragma unroll
    for (int pass = 0; pass < 2; ++pass) {
        const int i0 = pass * 64 + grp * 4;
        if (i0 < A1_ROWS) {
            unsigned long long aL[4] = {}, aH[4] = {}, dL[4] = {}, dH[4] = {};
            const int r0 = g0 + 2 * i0;
            if (r0 >= 0 && r0 <= 4096 - 14) {
                const ulonglong2* p = xb4 + (size_t)r0 * 16 + f4;
#pragma unroll
                for (int t = 0; t < 14; ++t) {
                    const ulonglong2 w = ldg_nc(p + t * 16);
                    ACC4(w.x, w.y, t)
                }
            } else {
#pragma unroll
                for (int t = 0; t < 14; ++t) {
                    const int r = (r0 + t + 4096) & 4095;
                    const ulonglong2 w = ldg_nc(xb4 + (size_t)r * 16 + f4);
                    ACC4(w.x, w.y, t)
                }
            }
#pragma unroll
            for (int q = 0; q < 4; ++q) {
                const int i = i0 + q;          // max 83 < A1_CAP
                s_a1[i * 16 + f4] = make_ulonglong2(aL[q], aH[q]);
                if (i >= 18 && i < A1_ROWS)
                    stg_cs(ob4 + (size_t)(2048 + 64 * tile + (i - 18)) * 16 + f4,
                           dL[q], dH[q]);
            }
        }
    }
    __syncthreads();

    // ---- Level 2: cA1 (smem) -> cA2 (smem) + cD2 (global) ----
    {
        const int i0 = grp * 4;
        if (i0 < A2_ROWS) {
            unsigned long long aL[4] = {}, aH[4] = {}, dL[4] = {}, dH[4] = {};
            const ulonglong2* p = s_a1 + (size_t)(2 * i0) * 16 + f4;
#pragma unroll
            for (int t = 0; t < 14; ++t) {
                const ulonglong2 w = p[t * 16];
                ACC4(w.x, w.y, t)
            }
#pragma unroll
            for (int q = 0; q < 4; ++q) {
                const int i = i0 + q;          // max 39 < A2_CAP
                s_a2[i * 16 + f4] = make_ulonglong2(aL[q], aH[q]);
                if (i >= 6 && i < A2_ROWS)
                    stg_cs(ob4 + (size_t)(1024 + 32 * tile + (i - 6)) * 16 + f4,
                           dL[q], dH[q]);
            }
        }
    }
    __syncthreads();

    // ---- Level 3: cA2 (smem) -> cA3 + cD3 (global) ----
    {
        const int i0 = grp * 4;
        if (i0 < 16) {
            unsigned long long aL[4] = {}, aH[4] = {}, dL[4] = {}, dH[4] = {};
            const ulonglong2* p = s_a2 + (size_t)(2 * i0) * 16 + f4;
#pragma unroll
            for (int t = 0; t < 14; ++t) {
                const ulonglong2 w = p[t * 16];
                ACC4(w.x, w.y, t)
            }
#pragma unroll
            for (int q = 0; q < 4; ++q) {
                const int i = i0 + q;
                stg_cs(ob4 + (size_t)(16 * tile + i) * 16 + f4, aL[q], aH[q]);
                stg_cs(ob4 + (size_t)(512 + 16 * tile + i) * 16 + f4, dL[q], dH[q]);
            }
        }
    }
}

extern "C" void kernel_launch(void* const* d_in, const int* in_sizes, int n_in,
                              void* d_out, int out_size) {
    const float* x = (const float*)d_in[0];
    float* out = (float*)d_out;
    dim3 grid(32, 64);
    wavedec_kernel<<<grid, NTHREADS>>>(x, out);
}